// round 6
// baseline (speedup 1.0000x reference)
#include <cuda_runtime.h>
#include <math.h>

// ---------------------------------------------------------------------------
// GPT-2 small forward. fp32 activations; GEMMs use split-tf32 (3xTF32)
// mma.sync. All GEMM operands are PRE-SPLIT (hi,lo) float2 in gmem, so the
// GEMM hot loop is pure LDG/STS/LDS/MMA with zero conversion arithmetic.
// ---------------------------------------------------------------------------

namespace {
constexpr int B_  = 4;
constexpr int T_  = 1024;
constexpr int C_  = 768;
constexpr int H_  = 12;
constexpr int HS_ = 64;
constexpr int L_  = 12;
constexpr int V_  = 32000;
constexpr int BT_ = B_ * T_;
constexpr int C4_ = 4 * C_;
constexpr int C3_ = 3 * C_;

constexpr int KT = 16;              // k per tile
constexpr int P  = 132;             // smem row pitch in float2
constexpr int STG = 2 * KT * P;     // float2 per stage (As + Bs)
constexpr size_t SMEM_BYTES = 2 * STG * sizeof(float2);   // 67584 B
}

// Scratch (no cudaMalloc -> device globals)
__device__ float  g_x   [BT_ * C_];
__device__ float2 g_h2  [BT_ * C_];
__device__ float2 g_qkv2[BT_ * C3_];
__device__ float2 g_o2  [BT_ * C_];
__device__ float2 g_a12 [BT_ * C4_];
__device__ float  g_att [(size_t)B_ * H_ * T_ * T_];
__device__ float2 g_att2[(size_t)B_ * H_ * T_ * T_];
__device__ float2 g_wcat2[C_ * C3_];
__device__ float2 g_wp2  [C_ * C_];
__device__ float2 g_w12  [C_ * C4_];
__device__ float2 g_w22  [C4_ * C_];
__device__ float2 g_wh2  [C_ * V_];

// ---------------------------------------------------------------------------
// tf32 helpers
// ---------------------------------------------------------------------------
__device__ __forceinline__ float2 tf32_split2(float x) {
    unsigned h;
    asm("cvt.rna.tf32.f32 %0, %1;" : "=r"(h) : "f"(x));
    float hf = __uint_as_float(h);
    float l  = x - hf;                       // exact in fp32
    unsigned lu;
    asm("cvt.rna.tf32.f32 %0, %1;" : "=r"(lu) : "f"(l));
    return make_float2(hf, __uint_as_float(lu));
}

__device__ __forceinline__ void mma_tf32(float* d, const unsigned* a, const unsigned* b) {
    asm volatile(
        "mma.sync.aligned.m16n8k8.row.col.f32.tf32.tf32.f32 "
        "{%0,%1,%2,%3}, {%4,%5,%6,%7}, {%8,%9}, {%0,%1,%2,%3};"
        : "+f"(d[0]), "+f"(d[1]), "+f"(d[2]), "+f"(d[3])
        : "r"(a[0]), "r"(a[1]), "r"(a[2]), "r"(a[3]),
          "r"(b[0]), "r"(b[1]));
}

// ---------------------------------------------------------------------------
// GEMM on pre-split operands.
//   A2: [M,K] logical, row-major, float2 (hi,lo) per element, leading dim lda.
//   B2: !transB -> [K,N]; transB -> [N,K] (A@B^T). Same float2 encoding.
//   C = alpha*A@B (+bias)(+gelu)(+resid[plain float]); output plain float or
//   split float2 (outSplit) so downstream GEMMs read it directly.
// Tile 128x128xKT, 256 threads. MT=2: warps 4x2, warp 32x64.
// MT=1 (N<=64): warps 8x1, warp 16x64.
// M%128==0, K%16==0 always; N guarded (N%64==0 so float4 groups whole).
// ---------------------------------------------------------------------------
template<int MT>
__global__ void __launch_bounds__(256)
gemm_tf32(const float2* __restrict__ A, const float2* __restrict__ Bp,
          float* __restrict__ Cp,
          int M, int N, int K, int lda, int ldb, int ldc,
          long long sAb, long long sAh, long long sBb, long long sBh,
          long long sCb, long long sCh, int nH,
          const float* __restrict__ bias, const float* __restrict__ resid,
          float alpha, int doGelu, int transB, int outSplit)
{
    extern __shared__ float2 smbuf[];

    int bz = blockIdx.z;
    int bb = bz / nH, hh = bz - bb * nH;
    A  += bb * sAb + hh * sAh;
    Bp += bb * sBb + hh * sBh;
    const float* Rp = resid ? (resid + bb * sCb + hh * sCh) : (const float*)0;

    int m0   = blockIdx.y << 7;
    int n0   = blockIdx.x << 7;
    int tid  = threadIdx.x;
    int lane = tid & 31;
    int wid  = tid >> 5;
    int wm   = (MT == 2) ? ((wid & 3) << 5) : (wid << 4);
    int wn   = (MT == 2) ? ((wid >> 2) << 6) : 0;

    float acc[MT][8][4];
    #pragma unroll
    for (int a = 0; a < MT; a++)
        #pragma unroll
        for (int b = 0; b < 8; b++)
            #pragma unroll
            for (int j = 0; j < 4; j++) acc[a][b][j] = 0.f;

    // loader patterns (all in float2 element units)
    const int la_m  = tid >> 2;             // 0..63 (row within half tile)
    const int la_k  = (tid & 3) << 2;       // 0,4,8,12
    const int lb_k  = tid >> 5;             // 0..7
    const int lb_n  = (tid & 31) << 2;      // 0..124

    float4 ra[2][2], rb[2][2];
    const int nk = K >> 4;

    auto LOAD = [&](int k0) {
        #pragma unroll
        for (int j = 0; j < 2; j++) {
            int m = la_m + (j << 6);
            const float4* p = (const float4*)(A + (size_t)(m0 + m) * lda + (k0 + la_k));
            ra[j][0] = p[0]; ra[j][1] = p[1];
        }
        if (transB) {
            #pragma unroll
            for (int j = 0; j < 2; j++) {
                int n = la_m + (j << 6);
                if (n0 + n < N) {
                    const float4* p = (const float4*)(Bp + (size_t)(n0 + n) * ldb + (k0 + la_k));
                    rb[j][0] = p[0]; rb[j][1] = p[1];
                } else {
                    rb[j][0] = make_float4(0.f,0.f,0.f,0.f);
                    rb[j][1] = make_float4(0.f,0.f,0.f,0.f);
                }
            }
        } else {
            #pragma unroll
            for (int j = 0; j < 2; j++) {
                int kk = lb_k + (j << 3);
                if (n0 + lb_n < N) {
                    const float4* p = (const float4*)(Bp + (size_t)(k0 + kk) * ldb + (n0 + lb_n));
                    rb[j][0] = p[0]; rb[j][1] = p[1];
                } else {
                    rb[j][0] = make_float4(0.f,0.f,0.f,0.f);
                    rb[j][1] = make_float4(0.f,0.f,0.f,0.f);
                }
            }
        }
    };

    auto STORE = [&](int s) {
        float2* As = smbuf + s * STG;
        float2* Bs = As + KT * P;
        #pragma unroll
        for (int j = 0; j < 2; j++) {
            int m = la_m + (j << 6);
            As[(la_k + 0) * P + m] = make_float2(ra[j][0].x, ra[j][0].y);
            As[(la_k + 1) * P + m] = make_float2(ra[j][0].z, ra[j][0].w);
            As[(la_k + 2) * P + m] = make_float2(ra[j][1].x, ra[j][1].y);
            As[(la_k + 3) * P + m] = make_float2(ra[j][1].z, ra[j][1].w);
        }
        if (transB) {
            #pragma unroll
            for (int j = 0; j < 2; j++) {
                int n = la_m + (j << 6);
                Bs[(la_k + 0) * P + n] = make_float2(rb[j][0].x, rb[j][0].y);
                Bs[(la_k + 1) * P + n] = make_float2(rb[j][0].z, rb[j][0].w);
                Bs[(la_k + 2) * P + n] = make_float2(rb[j][1].x, rb[j][1].y);
                Bs[(la_k + 3) * P + n] = make_float2(rb[j][1].z, rb[j][1].w);
            }
        } else {
            #pragma unroll
            for (int j = 0; j < 2; j++) {
                int kk = lb_k + (j << 3);
                *(float4*)&Bs[kk * P + lb_n]     = rb[j][0];
                *(float4*)&Bs[kk * P + lb_n + 2] = rb[j][1];
            }
        }
    };

    LOAD(0);
    STORE(0);
    __syncthreads();

    for (int t = 0; t < nk; t++) {
        if (t + 1 < nk) LOAD((t + 1) << 4);

        const float2* As = smbuf + (t & 1) * STG;
        const float2* Bs = As + KT * P;

        #pragma unroll
        for (int kk = 0; kk < 16; kk += 8) {
            int ck = kk + (lane & 3);
            int qd = lane >> 2;
            float2 af[MT][4];
            #pragma unroll
            for (int mt = 0; mt < MT; mt++) {
                int r = wm + (mt << 4) + qd;
                af[mt][0] = As[ck * P + r];
                af[mt][1] = As[ck * P + r + 8];
                af[mt][2] = As[(ck + 4) * P + r];
                af[mt][3] = As[(ck + 4) * P + r + 8];
            }
            float2 bf[8][2];
            #pragma unroll
            for (int nt = 0; nt < 8; nt++) {
                int cn = wn + (nt << 3) + qd;
                bf[nt][0] = Bs[ck * P + cn];
                bf[nt][1] = Bs[(ck + 4) * P + cn];
            }
            #pragma unroll
            for (int mt = 0; mt < MT; mt++) {
                unsigned ah[4], al[4];
                #pragma unroll
                for (int i2 = 0; i2 < 4; i2++) {
                    ah[i2] = __float_as_uint(af[mt][i2].x);
                    al[i2] = __float_as_uint(af[mt][i2].y);
                }
                #pragma unroll
                for (int nt = 0; nt < 8; nt++) {
                    unsigned bh[2] = {__float_as_uint(bf[nt][0].x), __float_as_uint(bf[nt][1].x)};
                    unsigned bl[2] = {__float_as_uint(bf[nt][0].y), __float_as_uint(bf[nt][1].y)};
                    mma_tf32(acc[mt][nt], ah, bh);
                    mma_tf32(acc[mt][nt], ah, bl);
                    mma_tf32(acc[mt][nt], al, bh);
                }
            }
        }

        if (t + 1 < nk) STORE((t + 1) & 1);
        __syncthreads();
    }

    // ---- epilogue ----
    float*  Co = Cp + bb * sCb + hh * sCh;
    float2* C2 = (float2*)Cp + bb * sCb + hh * sCh;
    #pragma unroll
    for (int mt = 0; mt < MT; mt++) {
        #pragma unroll
        for (int nt = 0; nt < 8; nt++) {
            int row = m0 + wm + (mt << 4) + (lane >> 2);
            int col = n0 + wn + (nt << 3) + ((lane & 3) << 1);
            #pragma unroll
            for (int j = 0; j < 4; j++) {
                int r = row + ((j & 2) ? 8 : 0);
                int c = col + (j & 1);
                if (c < N) {
                    float v2 = acc[mt][nt][j] * alpha;
                    if (bias) v2 += bias[c];
                    if (doGelu) v2 = 0.5f * v2 * (1.f + erff(v2 * 0.70710678118654752f));
                    if (Rp) v2 += Rp[(size_t)r * ldc + c];
                    if (outSplit) C2[(size_t)r * ldc + c] = tf32_split2(v2);
                    else          Co[(size_t)r * ldc + c] = v2;
                }
            }
        }
    }
}

// ---------------------------------------------------------------------------
// Elementwise split: dst[i] = (tf32hi, tf32lo) of src[i]. n % 4 == 0.
// ---------------------------------------------------------------------------
__global__ void split_k(const float* __restrict__ src, float2* __restrict__ dst, int n4)
{
    int i = blockIdx.x * 256 + threadIdx.x;
    if (i < n4) {
        float4 v = ((const float4*)src)[i];
        dst[4 * i + 0] = tf32_split2(v.x);
        dst[4 * i + 1] = tf32_split2(v.y);
        dst[4 * i + 2] = tf32_split2(v.z);
        dst[4 * i + 3] = tf32_split2(v.w);
    }
}

// Pack per-layer Wq/Wk/Wv [C,C] into split Wcat2 [C, 3C]
__global__ void pack_qkv_split(const float* __restrict__ Wq, const float* __restrict__ Wk,
                               const float* __restrict__ Wv, float2* __restrict__ Wcat)
{
    int i = blockIdx.x * 256 + threadIdx.x;
    if (i < C_ * C_) {
        int k = i / C_, j = i - k * C_;
        Wcat[(size_t)k * C3_ + j]          = tf32_split2(Wq[i]);
        Wcat[(size_t)k * C3_ + C_ + j]     = tf32_split2(Wk[i]);
        Wcat[(size_t)k * C3_ + 2 * C_ + j] = tf32_split2(Wv[i]);
    }
}

// ---------------------------------------------------------------------------
// LayerNorm (biased variance, eps=1e-5) -> split float2 output
// ---------------------------------------------------------------------------
__global__ void layernorm_split(const float* __restrict__ x, const float* __restrict__ g,
                                const float* __restrict__ b, float2* __restrict__ y)
{
    int row = blockIdx.x;
    const float* xr = x + (size_t)row * C_;
    float2* yr      = y + (size_t)row * C_;
    int tid = threadIdx.x;
    float s = 0.f, s2 = 0.f;
    for (int c = tid; c < C_; c += 256) { float v = xr[c]; s += v; s2 += v * v; }
    __shared__ float shs[8], shs2[8];
    #pragma unroll
    for (int o = 16; o; o >>= 1) {
        s  += __shfl_xor_sync(0xffffffffu, s,  o);
        s2 += __shfl_xor_sync(0xffffffffu, s2, o);
    }
    if ((tid & 31) == 0) { shs[tid >> 5] = s; shs2[tid >> 5] = s2; }
    __syncthreads();
    float ts = 0.f, ts2 = 0.f;
    #pragma unroll
    for (int i = 0; i < 8; i++) { ts += shs[i]; ts2 += shs2[i]; }
    float mean = ts * (1.f / C_);
    float var  = ts2 * (1.f / C_) - mean * mean;
    float rstd = rsqrtf(var + 1e-5f);
    for (int c = tid; c < C_; c += 256)
        yr[c] = tf32_split2((xr[c] - mean) * rstd * g[c] + b[c]);
}

// ---------------------------------------------------------------------------
// Causal softmax: read plain att, write split att2 (tail zeros).
// ---------------------------------------------------------------------------
__global__ void softmax_causal(const float* __restrict__ att, float2* __restrict__ att2)
{
    int row = blockIdx.x;             // b*H*T + h*T + q
    int q   = row & (T_ - 1);
    const float* a = att + (size_t)row * T_;
    float2* o2     = att2 + (size_t)row * T_;
    int len = q + 1;
    int tid = threadIdx.x;
    __shared__ float sh[8];

    float r[4];
    #pragma unroll
    for (int i = 0; i < 4; i++) {
        int c = tid + (i << 8);
        r[i] = (c < len) ? a[c] : -3.0e38f;
    }
    float mx = fmaxf(fmaxf(r[0], r[1]), fmaxf(r[2], r[3]));
    #pragma unroll
    for (int o = 16; o; o >>= 1) mx = fmaxf(mx, __shfl_xor_sync(0xffffffffu, mx, o));
    if ((tid & 31) == 0) sh[tid >> 5] = mx;
    __syncthreads();
    mx = sh[0];
    #pragma unroll
    for (int i = 1; i < 8; i++) mx = fmaxf(mx, sh[i]);
    __syncthreads();

    float s = 0.f;
    #pragma unroll
    for (int i = 0; i < 4; i++) {
        int c = tid + (i << 8);
        r[i] = (c < len) ? expf(r[i] - mx) : 0.f;
        s += r[i];
    }
    #pragma unroll
    for (int o = 16; o; o >>= 1) s += __shfl_xor_sync(0xffffffffu, s, o);
    if ((tid & 31) == 0) sh[tid >> 5] = s;
    __syncthreads();
    float tot = 0.f;
    #pragma unroll
    for (int i = 0; i < 8; i++) tot += sh[i];
    float inv = 1.f / tot;

    #pragma unroll
    for (int i = 0; i < 4; i++) {
        int c = tid + (i << 8);
        o2[c] = tf32_split2(r[i] * inv);
    }
}

// ---------------------------------------------------------------------------
// Embedding
// ---------------------------------------------------------------------------
__global__ void embed_k(const int* __restrict__ idx, const float* __restrict__ tok,
                        const float* __restrict__ pos, float* __restrict__ x)
{
    int r = blockIdx.x;
    int t = r & (T_ - 1);
    int token = idx[r];
    const float* te = tok + (size_t)token * C_;
    const float* pe = pos + (size_t)t * C_;
    float* xr = x + (size_t)r * C_;
    for (int c = threadIdx.x; c < C_; c += 256) xr[c] = te[c] + pe[c];
}

// ---------------------------------------------------------------------------
// Launch
// ---------------------------------------------------------------------------
extern "C" void kernel_launch(void* const* d_in, const int* in_sizes, int n_in,
                              void* d_out, int out_size)
{
    (void)in_sizes; (void)n_in; (void)out_size;
    const int*   idx = (const int*)d_in[0];
    const float* tok = (const float*)d_in[1];
    const float* pos = (const float*)d_in[2];
    const float* Wq  = (const float*)d_in[3];
    const float* Wk  = (const float*)d_in[4];
    const float* Wv  = (const float*)d_in[5];
    const float* Wp  = (const float*)d_in[6];
    const float* bp  = (const float*)d_in[7];
    const float* g1  = (const float*)d_in[8];
    const float* be1 = (const float*)d_in[9];
    const float* g2  = (const float*)d_in[10];
    const float* be2 = (const float*)d_in[11];
    const float* W1  = (const float*)d_in[12];
    const float* bb1 = (const float*)d_in[13];
    const float* W2  = (const float*)d_in[14];
    const float* bb2 = (const float*)d_in[15];
    const float* gf  = (const float*)d_in[16];
    const float* bf  = (const float*)d_in[17];
    const float* Wh  = (const float*)d_in[18];
    const float* bhd = (const float*)d_in[19];
    float* out = (float*)d_out;

    float  *x, *att;
    float2 *h2, *qkv2, *o2, *a12, *att2, *wcat2, *wp2, *w12, *w22, *wh2;
    cudaGetSymbolAddress((void**)&x,     g_x);
    cudaGetSymbolAddress((void**)&h2,    g_h2);
    cudaGetSymbolAddress((void**)&qkv2,  g_qkv2);
    cudaGetSymbolAddress((void**)&o2,    g_o2);
    cudaGetSymbolAddress((void**)&a12,   g_a12);
    cudaGetSymbolAddress((void**)&att,   g_att);
    cudaGetSymbolAddress((void**)&att2,  g_att2);
    cudaGetSymbolAddress((void**)&wcat2, g_wcat2);
    cudaGetSymbolAddress((void**)&wp2,   g_wp2);
    cudaGetSymbolAddress((void**)&w12,   g_w12);
    cudaGetSymbolAddress((void**)&w22,   g_w22);
    cudaGetSymbolAddress((void**)&wh2,   g_wh2);

    cudaFuncSetAttribute((const void*)gemm_tf32<2>,
                         cudaFuncAttributeMaxDynamicSharedMemorySize, (int)SMEM_BYTES);
    cudaFuncSetAttribute((const void*)gemm_tf32<1>,
                         cudaFuncAttributeMaxDynamicSharedMemorySize, (int)SMEM_BYTES);

    const float att_scale = 0.03608439182435161f;  // 768^-0.5 (reference uses full C)
    const float* NOF = (const float*)0;

    embed_k<<<BT_, 256>>>(idx, tok, pos, x);

    // split head weights once
    split_k<<<(C_ * V_ / 4 + 255) / 256, 256>>>(Wh, wh2, C_ * V_ / 4);

    dim3 gqkv(C3_ / 128, BT_ / 128, 1);
    dim3 gcc (C_  / 128, BT_ / 128, 1);
    dim3 gsc (T_  / 128, T_  / 128, B_ * H_);
    dim3 gav (1,         T_  / 128, B_ * H_);
    dim3 gf1 (C4_ / 128, BT_ / 128, 1);

    for (int l = 0; l < L_; l++) {
        // per-layer weight splits
        pack_qkv_split<<<(C_ * C_ + 255) / 256, 256>>>(Wq + (size_t)l * C_ * C_,
                                                       Wk + (size_t)l * C_ * C_,
                                                       Wv + (size_t)l * C_ * C_, wcat2);
        split_k<<<(C_ * C_  / 4 + 255) / 256, 256>>>(Wp + (size_t)l * C_ * C_,  wp2, C_ * C_  / 4);
        split_k<<<(C_ * C4_ / 4 + 255) / 256, 256>>>(W1 + (size_t)l * C_ * C4_, w12, C_ * C4_ / 4);
        split_k<<<(C4_ * C_ / 4 + 255) / 256, 256>>>(W2 + (size_t)l * C4_ * C_, w22, C4_ * C_ / 4);

        layernorm_split<<<BT_, 256>>>(x, g1 + l * C_, be1 + l * C_, h2);

        // qkv = h @ Wcat -> split [BT, 3C]
        gemm_tf32<2><<<gqkv, 256, SMEM_BYTES>>>(h2, wcat2, (float*)qkv2,
                BT_, C3_, C_, C_, C3_, C3_,
                0, 0, 0, 0, 0, 0, 1, NOF, NOF, 1.f, 0, 0, 1);

        // scores: Q @ K^T per (b,h) -> plain att
        gemm_tf32<2><<<gsc, 256, SMEM_BYTES>>>(qkv2, qkv2 + C_, att,
                T_, T_, HS_, C3_, C3_, T_,
                (long long)T_ * C3_, (long long)HS_,
                (long long)T_ * C3_, (long long)HS_,
                (long long)H_ * T_ * T_, (long long)T_ * T_, H_,
                NOF, NOF, att_scale, 0, 1, 0);

        softmax_causal<<<B_ * H_ * T_, 256>>>(att, att2);

        // AV: P @ V -> split o
        gemm_tf32<1><<<gav, 256, SMEM_BYTES>>>(att2, qkv2 + 2 * C_, (float*)o2,
                T_, HS_, T_, T_, C3_, C_,
                (long long)H_ * T_ * T_, (long long)T_ * T_,
                (long long)T_ * C3_, (long long)HS_,
                (long long)T_ * C_, (long long)HS_, H_,
                NOF, NOF, 1.f, 0, 0, 1);

        // x = x + o @ Wproj + bproj (plain out)
        gemm_tf32<2><<<gcc, 256, SMEM_BYTES>>>(o2, wp2, x,
                BT_, C_, C_, C_, C_, C_,
                0, 0, 0, 0, 0, 0, 1, bp + l * C_, x, 1.f, 0, 0, 0);

        layernorm_split<<<BT_, 256>>>(x, g2 + l * C_, be2 + l * C_, h2);

        // a1 = gelu(h @ W1 + b1) -> split
        gemm_tf32<2><<<gf1, 256, SMEM_BYTES>>>(h2, w12, (float*)a12,
                BT_, C4_, C_, C_, C4_, C4_,
                0, 0, 0, 0, 0, 0, 1, bb1 + l * C4_, NOF, 1.f, 1, 0, 1);

        // x = x + a1 @ W2 + b2 (plain out)
        gemm_tf32<2><<<gcc, 256, SMEM_BYTES>>>(a12, w22, x,
                BT_, C_, C4_, C4_, C_, C_,
                0, 0, 0, 0, 0, 0, 1, bb2 + l * C_, x, 1.f, 0, 0, 0);
    }

    layernorm_split<<<BT_, 256>>>(x, gf, bf, h2);

    dim3 ghd(V_ / 128, BT_ / 128, 1);
    gemm_tf32<2><<<ghd, 256, SMEM_BYTES>>>(h2, wh2, out,
            BT_, V_, C_, C_, V_, V_,
            0, 0, 0, 0, 0, 0, 1, bhd, NOF, 1.f, 0, 0, 0);
}

// round 7
// speedup vs baseline: 1.1296x; 1.1296x over previous
#include <cuda_runtime.h>
#include <math.h>

// ---------------------------------------------------------------------------
// GPT-2 small forward. fp32 activations; GEMMs use split-tf32 (3xTF32)
// mma.sync. Weights/activations feeding GEMMs are pre-split (hi,lo) float2.
// 512-thread GEMM CTAs (16 warps) for latency hiding; causal-aware attention.
// ---------------------------------------------------------------------------

namespace {
constexpr int B_  = 4;
constexpr int T_  = 1024;
constexpr int C_  = 768;
constexpr int H_  = 12;
constexpr int HS_ = 64;
constexpr int L_  = 12;
constexpr int V_  = 32000;
constexpr int BT_ = B_ * T_;
constexpr int C4_ = 4 * C_;
constexpr int C3_ = 3 * C_;

constexpr int KT = 16;              // k per tile
constexpr int P  = 132;             // smem row pitch in float2
constexpr int STG = 2 * KT * P;     // float2 per stage (As + Bs)
constexpr size_t SMEM_BYTES = 2 * STG * sizeof(float2);   // 67584 B
}

// Scratch (no cudaMalloc -> device globals)
__device__ float  g_x   [BT_ * C_];
__device__ float2 g_h2  [BT_ * C_];
__device__ float2 g_qkv2[BT_ * C3_];
__device__ float2 g_o2  [BT_ * C_];
__device__ float2 g_a12 [BT_ * C4_];
__device__ float  g_att [(size_t)B_ * H_ * T_ * T_];
// all-layer pre-split weights
__device__ float2 g_wcat2[(size_t)L_ * C_ * C3_];
__device__ float2 g_wp2  [(size_t)L_ * C_ * C_];
__device__ float2 g_w12  [(size_t)L_ * C_ * C4_];
__device__ float2 g_w22  [(size_t)L_ * C4_ * C_];
__device__ float2 g_wh2  [(size_t)C_ * V_];

// ---------------------------------------------------------------------------
// tf32 helpers
// ---------------------------------------------------------------------------
__device__ __forceinline__ float2 tf32_split2(float x) {
    unsigned h;
    asm("cvt.rna.tf32.f32 %0, %1;" : "=r"(h) : "f"(x));
    float hf = __uint_as_float(h);
    float l  = x - hf;                       // exact in fp32
    unsigned lu;
    asm("cvt.rna.tf32.f32 %0, %1;" : "=r"(lu) : "f"(l));
    return make_float2(hf, __uint_as_float(lu));
}

__device__ __forceinline__ void mma_tf32(float* d, const unsigned* a, const unsigned* b) {
    asm volatile(
        "mma.sync.aligned.m16n8k8.row.col.f32.tf32.tf32.f32 "
        "{%0,%1,%2,%3}, {%4,%5,%6,%7}, {%8,%9}, {%0,%1,%2,%3};"
        : "+f"(d[0]), "+f"(d[1]), "+f"(d[2]), "+f"(d[3])
        : "r"(a[0]), "r"(a[1]), "r"(a[2]), "r"(a[3]),
          "r"(b[0]), "r"(b[1]));
}

// ---------------------------------------------------------------------------
// Main GEMM: 512 threads, tile 128x128xKT, 16 warps (4x4), warp tile 32x32.
// A2,B2 pre-split float2. C = alpha*A@B (+bias)(+gelu)(+resid); out plain or
// split. causalSkip: skip blocks with bx > by (upper-triangular score blocks).
// M%128==0, K%16==0; N guarded in units of 4 (all N here %64==0).
// ---------------------------------------------------------------------------
__global__ void __launch_bounds__(512)
gemm512(const float2* __restrict__ A, const float2* __restrict__ Bp,
        float* __restrict__ Cp,
        int M, int N, int K, int lda, int ldb, int ldc,
        long long sAb, long long sAh, long long sBb, long long sBh,
        long long sCb, long long sCh, int nH,
        const float* __restrict__ bias, const float* __restrict__ resid,
        float alpha, int doGelu, int transB, int outSplit, int causalSkip)
{
    if (causalSkip && blockIdx.x > blockIdx.y) return;
    extern __shared__ float2 smbuf[];

    int bz = blockIdx.z;
    int bb = bz / nH, hh = bz - bb * nH;
    A  += bb * sAb + hh * sAh;
    Bp += bb * sBb + hh * sBh;
    const float* Rp = resid ? (resid + bb * sCb + hh * sCh) : (const float*)0;

    int m0   = blockIdx.y << 7;
    int n0   = blockIdx.x << 7;
    int tid  = threadIdx.x;
    int lane = tid & 31;
    int wid  = tid >> 5;
    int wm   = (wid & 3) << 5;      // 0,32,64,96
    int wn   = (wid >> 2) << 5;     // 0,32,64,96

    float acc[2][4][4];
    #pragma unroll
    for (int a = 0; a < 2; a++)
        #pragma unroll
        for (int b = 0; b < 4; b++)
            #pragma unroll
            for (int j = 0; j < 4; j++) acc[a][b][j] = 0.f;

    // loader patterns (float2 element units)
    const int la_m = tid >> 2;              // 0..127
    const int la_k = (tid & 3) << 2;        // 0,4,8,12
    const int lb_k = tid >> 5;              // 0..15
    const int lb_n = (tid & 31) << 2;       // 0..124

    float4 ra[2], rb[2];
    const int nk = K >> 4;

    auto LOAD = [&](int k0) {
        {
            const float4* p = (const float4*)(A + (size_t)(m0 + la_m) * lda + (k0 + la_k));
            ra[0] = p[0]; ra[1] = p[1];
        }
        if (transB) {
            if (n0 + la_m < N) {
                const float4* p = (const float4*)(Bp + (size_t)(n0 + la_m) * ldb + (k0 + la_k));
                rb[0] = p[0]; rb[1] = p[1];
            } else {
                rb[0] = make_float4(0.f,0.f,0.f,0.f);
                rb[1] = make_float4(0.f,0.f,0.f,0.f);
            }
        } else {
            if (n0 + lb_n < N) {
                const float4* p = (const float4*)(Bp + (size_t)(k0 + lb_k) * ldb + (n0 + lb_n));
                rb[0] = p[0]; rb[1] = p[1];
            } else {
                rb[0] = make_float4(0.f,0.f,0.f,0.f);
                rb[1] = make_float4(0.f,0.f,0.f,0.f);
            }
        }
    };

    auto STORE = [&](int s) {
        float2* As = smbuf + s * STG;
        float2* Bs = As + KT * P;
        As[(la_k + 0) * P + la_m] = make_float2(ra[0].x, ra[0].y);
        As[(la_k + 1) * P + la_m] = make_float2(ra[0].z, ra[0].w);
        As[(la_k + 2) * P + la_m] = make_float2(ra[1].x, ra[1].y);
        As[(la_k + 3) * P + la_m] = make_float2(ra[1].z, ra[1].w);
        if (transB) {
            Bs[(la_k + 0) * P + la_m] = make_float2(rb[0].x, rb[0].y);
            Bs[(la_k + 1) * P + la_m] = make_float2(rb[0].z, rb[0].w);
            Bs[(la_k + 2) * P + la_m] = make_float2(rb[1].x, rb[1].y);
            Bs[(la_k + 3) * P + la_m] = make_float2(rb[1].z, rb[1].w);
        } else {
            *(float4*)&Bs[lb_k * P + lb_n]     = rb[0];
            *(float4*)&Bs[lb_k * P + lb_n + 2] = rb[1];
        }
    };

    LOAD(0);
    STORE(0);
    __syncthreads();

    for (int t = 0; t < nk; t++) {
        if (t + 1 < nk) LOAD((t + 1) << 4);

        const float2* As = smbuf + (t & 1) * STG;
        const float2* Bs = As + KT * P;

        #pragma unroll
        for (int kk = 0; kk < 16; kk += 8) {
            int ck = kk + (lane & 3);
            int qd = lane >> 2;
            float2 af[2][4];
            #pragma unroll
            for (int mt = 0; mt < 2; mt++) {
                int r = wm + (mt << 4) + qd;
                af[mt][0] = As[ck * P + r];
                af[mt][1] = As[ck * P + r + 8];
                af[mt][2] = As[(ck + 4) * P + r];
                af[mt][3] = As[(ck + 4) * P + r + 8];
            }
            float2 bf[4][2];
            #pragma unroll
            for (int nt = 0; nt < 4; nt++) {
                int cn = wn + (nt << 3) + qd;
                bf[nt][0] = Bs[ck * P + cn];
                bf[nt][1] = Bs[(ck + 4) * P + cn];
            }
            #pragma unroll
            for (int mt = 0; mt < 2; mt++) {
                unsigned ah[4], al[4];
                #pragma unroll
                for (int i2 = 0; i2 < 4; i2++) {
                    ah[i2] = __float_as_uint(af[mt][i2].x);
                    al[i2] = __float_as_uint(af[mt][i2].y);
                }
                #pragma unroll
                for (int nt = 0; nt < 4; nt++) {
                    unsigned bh[2] = {__float_as_uint(bf[nt][0].x), __float_as_uint(bf[nt][1].x)};
                    unsigned bl[2] = {__float_as_uint(bf[nt][0].y), __float_as_uint(bf[nt][1].y)};
                    mma_tf32(acc[mt][nt], ah, bh);
                    mma_tf32(acc[mt][nt], ah, bl);
                    mma_tf32(acc[mt][nt], al, bh);
                }
            }
        }

        if (t + 1 < nk) STORE((t + 1) & 1);
        __syncthreads();
    }

    // ---- epilogue ----
    float*  Co = Cp + bb * sCb + hh * sCh;
    float2* C2 = (float2*)Cp + bb * sCb + hh * sCh;
    #pragma unroll
    for (int mt = 0; mt < 2; mt++) {
        #pragma unroll
        for (int nt = 0; nt < 4; nt++) {
            int row = m0 + wm + (mt << 4) + (lane >> 2);
            int col = n0 + wn + (nt << 3) + ((lane & 3) << 1);
            #pragma unroll
            for (int j = 0; j < 4; j++) {
                int r = row + ((j & 2) ? 8 : 0);
                int c = col + (j & 1);
                if (c < N) {
                    float v2 = acc[mt][nt][j] * alpha;
                    if (bias) v2 += bias[c];
                    if (doGelu) v2 = 0.5f * v2 * (1.f + erff(v2 * 0.70710678118654752f));
                    if (Rp) v2 += Rp[(size_t)r * ldc + c];
                    if (outSplit) C2[(size_t)r * ldc + c] = tf32_split2(v2);
                    else          Co[(size_t)r * ldc + c] = v2;
                }
            }
        }
    }
}

// ---------------------------------------------------------------------------
// AV GEMM: o[b,h] = P[1024,1024] @ V[1024,64]. 256 threads, warp tile 16x64
// (8 warps x 1). A is PLAIN float (att), split during smem store (each P tile
// is loaded exactly once -> no redundancy). K clamped causally per block row.
// Output split float2.
// ---------------------------------------------------------------------------
__global__ void __launch_bounds__(256)
gemm_av(const float* __restrict__ A, const float2* __restrict__ Bp,
        float2* __restrict__ Cp,
        int K, int lda, int ldb, int ldc,
        long long sAb, long long sAh, long long sBb, long long sBh,
        long long sCb, long long sCh, int nH)
{
    extern __shared__ float2 smbuf[];
    constexpr int N = HS_;

    int bz = blockIdx.z;
    int bb = bz / nH, hh = bz - bb * nH;
    A  += bb * sAb + hh * sAh;
    Bp += bb * sBb + hh * sBh;
    float2* C2 = Cp + bb * sCb + hh * sCh;

    int m0   = blockIdx.y << 7;
    int tid  = threadIdx.x;
    int lane = tid & 31;
    int wid  = tid >> 5;
    int wm   = wid << 4;

    int K_eff = m0 + 128;           // causal: keys <= last query in this block
    if (K_eff > K) K_eff = K;
    const int nk = K_eff >> 4;

    float acc[8][4];
    #pragma unroll
    for (int b = 0; b < 8; b++)
        #pragma unroll
        for (int j = 0; j < 4; j++) acc[b][j] = 0.f;

    const int la_m = tid >> 2;              // 0..63 (+64 for j=1)
    const int la_k = (tid & 3) << 2;
    const int lb_k = tid >> 5;              // 0..7 (+8 for j=1)
    const int lb_n = (tid & 31) << 2;       // 0..124

    float4 ra[2], rb[2][2];

    auto LOAD = [&](int k0) {
        #pragma unroll
        for (int j = 0; j < 2; j++) {
            int m = la_m + (j << 6);
            ra[j] = *(const float4*)(A + (size_t)(m0 + m) * lda + (k0 + la_k));
        }
        #pragma unroll
        for (int j = 0; j < 2; j++) {
            int kk = lb_k + (j << 3);
            if (lb_n < N) {
                const float4* p = (const float4*)(Bp + (size_t)(k0 + kk) * ldb + lb_n);
                rb[j][0] = p[0]; rb[j][1] = p[1];
            } else {
                rb[j][0] = make_float4(0.f,0.f,0.f,0.f);
                rb[j][1] = make_float4(0.f,0.f,0.f,0.f);
            }
        }
    };

    auto STORE = [&](int s) {
        float2* As = smbuf + s * STG;
        float2* Bs = As + KT * P;
        #pragma unroll
        for (int j = 0; j < 2; j++) {
            int m = la_m + (j << 6);
            float v[4] = {ra[j].x, ra[j].y, ra[j].z, ra[j].w};
            #pragma unroll
            for (int q = 0; q < 4; q++)
                As[(la_k + q) * P + m] = tf32_split2(v[q]);
        }
        #pragma unroll
        for (int j = 0; j < 2; j++) {
            int kk = lb_k + (j << 3);
            *(float4*)&Bs[kk * P + lb_n]     = rb[j][0];
            *(float4*)&Bs[kk * P + lb_n + 2] = rb[j][1];
        }
    };

    LOAD(0);
    STORE(0);
    __syncthreads();

    for (int t = 0; t < nk; t++) {
        if (t + 1 < nk) LOAD((t + 1) << 4);

        const float2* As = smbuf + (t & 1) * STG;
        const float2* Bs = As + KT * P;

        #pragma unroll
        for (int kk = 0; kk < 16; kk += 8) {
            int ck = kk + (lane & 3);
            int qd = lane >> 2;
            float2 af[4];
            {
                int r = wm + qd;
                af[0] = As[ck * P + r];
                af[1] = As[ck * P + r + 8];
                af[2] = As[(ck + 4) * P + r];
                af[3] = As[(ck + 4) * P + r + 8];
            }
            unsigned ah[4], al[4];
            #pragma unroll
            for (int i2 = 0; i2 < 4; i2++) {
                ah[i2] = __float_as_uint(af[i2].x);
                al[i2] = __float_as_uint(af[i2].y);
            }
            #pragma unroll
            for (int nt = 0; nt < 8; nt++) {
                int cn = (nt << 3) + qd;
                float2 b0 = Bs[ck * P + cn];
                float2 b1 = Bs[(ck + 4) * P + cn];
                unsigned bh[2] = {__float_as_uint(b0.x), __float_as_uint(b1.x)};
                unsigned bl[2] = {__float_as_uint(b0.y), __float_as_uint(b1.y)};
                mma_tf32(acc[nt], ah, bh);
                mma_tf32(acc[nt], ah, bl);
                mma_tf32(acc[nt], al, bh);
            }
        }

        if (t + 1 < nk) STORE((t + 1) & 1);
        __syncthreads();
    }

    #pragma unroll
    for (int nt = 0; nt < 8; nt++) {
        int row = m0 + wm + (lane >> 2);
        int col = (nt << 3) + ((lane & 3) << 1);
        #pragma unroll
        for (int j = 0; j < 4; j++) {
            int r = row + ((j & 2) ? 8 : 0);
            int c = col + (j & 1);
            if (c < N)
                C2[(size_t)r * ldc + c] = tf32_split2(acc[nt][j]);
        }
    }
}

// ---------------------------------------------------------------------------
// Elementwise split (batched over all layers): dst[i]=(hi,lo) of src[i].
// ---------------------------------------------------------------------------
__global__ void split_k(const float* __restrict__ src, float2* __restrict__ dst, int n4)
{
    int i = blockIdx.x * 256 + threadIdx.x;
    if (i < n4) {
        float4 v = ((const float4*)src)[i];
        dst[4 * i + 0] = tf32_split2(v.x);
        dst[4 * i + 1] = tf32_split2(v.y);
        dst[4 * i + 2] = tf32_split2(v.z);
        dst[4 * i + 3] = tf32_split2(v.w);
    }
}

// Pack Wq/Wk/Wv [L,C,C] into split Wcat2 [L][C][3C], all layers at once.
__global__ void pack_qkv_split(const float* __restrict__ Wq, const float* __restrict__ Wk,
                               const float* __restrict__ Wv, float2* __restrict__ Wcat)
{
    int i = blockIdx.x * 256 + threadIdx.x;
    if (i < L_ * C_ * C_) {
        int l = i / (C_ * C_);
        int r = i - l * (C_ * C_);
        int k = r / C_, j = r - k * C_;
        float2* W = Wcat + (size_t)l * C_ * C3_;
        W[(size_t)k * C3_ + j]          = tf32_split2(Wq[i]);
        W[(size_t)k * C3_ + C_ + j]     = tf32_split2(Wk[i]);
        W[(size_t)k * C3_ + 2 * C_ + j] = tf32_split2(Wv[i]);
    }
}

// ---------------------------------------------------------------------------
// LayerNorm (biased variance, eps=1e-5) -> split float2 output
// ---------------------------------------------------------------------------
__global__ void layernorm_split(const float* __restrict__ x, const float* __restrict__ g,
                                const float* __restrict__ b, float2* __restrict__ y)
{
    int row = blockIdx.x;
    const float* xr = x + (size_t)row * C_;
    float2* yr      = y + (size_t)row * C_;
    int tid = threadIdx.x;
    float s = 0.f, s2 = 0.f;
    for (int c = tid; c < C_; c += 256) { float v = xr[c]; s += v; s2 += v * v; }
    __shared__ float shs[8], shs2[8];
    #pragma unroll
    for (int o = 16; o; o >>= 1) {
        s  += __shfl_xor_sync(0xffffffffu, s,  o);
        s2 += __shfl_xor_sync(0xffffffffu, s2, o);
    }
    if ((tid & 31) == 0) { shs[tid >> 5] = s; shs2[tid >> 5] = s2; }
    __syncthreads();
    float ts = 0.f, ts2 = 0.f;
    #pragma unroll
    for (int i = 0; i < 8; i++) { ts += shs[i]; ts2 += shs2[i]; }
    float mean = ts * (1.f / C_);
    float var  = ts2 * (1.f / C_) - mean * mean;
    float rstd = rsqrtf(var + 1e-5f);
    for (int c = tid; c < C_; c += 256)
        yr[c] = tf32_split2((xr[c] - mean) * rstd * g[c] + b[c]);
}

// ---------------------------------------------------------------------------
// Causal softmax in place; read only valid prefix, write only to the next
// 128-boundary (AV GEMM's clamped K never reads beyond it).
// ---------------------------------------------------------------------------
__global__ void softmax_causal(float* __restrict__ att)
{
    int row = blockIdx.x;             // b*H*T + h*T + q
    int q   = row & (T_ - 1);
    float* a = att + (size_t)row * T_;
    int len  = q + 1;
    int wlim = ((q >> 7) + 1) << 7;
    int tid  = threadIdx.x;
    __shared__ float sh[8];

    float r[4];
    #pragma unroll
    for (int i = 0; i < 4; i++) {
        int c = tid + (i << 8);
        r[i] = (c < len) ? a[c] : -3.0e38f;
    }
    float mx = fmaxf(fmaxf(r[0], r[1]), fmaxf(r[2], r[3]));
    #pragma unroll
    for (int o = 16; o; o >>= 1) mx = fmaxf(mx, __shfl_xor_sync(0xffffffffu, mx, o));
    if ((tid & 31) == 0) sh[tid >> 5] = mx;
    __syncthreads();
    mx = sh[0];
    #pragma unroll
    for (int i = 1; i < 8; i++) mx = fmaxf(mx, sh[i]);
    __syncthreads();

    float s = 0.f;
    #pragma unroll
    for (int i = 0; i < 4; i++) {
        int c = tid + (i << 8);
        r[i] = (c < len) ? expf(r[i] - mx) : 0.f;
        s += r[i];
    }
    #pragma unroll
    for (int o = 16; o; o >>= 1) s += __shfl_xor_sync(0xffffffffu, s, o);
    if ((tid & 31) == 0) sh[tid >> 5] = s;
    __syncthreads();
    float tot = 0.f;
    #pragma unroll
    for (int i = 0; i < 8; i++) tot += sh[i];
    float inv = 1.f / tot;

    #pragma unroll
    for (int i = 0; i < 4; i++) {
        int c = tid + (i << 8);
        if (c < wlim) a[c] = r[i] * inv;
    }
}

// ---------------------------------------------------------------------------
// Embedding
// ---------------------------------------------------------------------------
__global__ void embed_k(const int* __restrict__ idx, const float* __restrict__ tok,
                        const float* __restrict__ pos, float* __restrict__ x)
{
    int r = blockIdx.x;
    int t = r & (T_ - 1);
    int token = idx[r];
    const float* te = tok + (size_t)token * C_;
    const float* pe = pos + (size_t)t * C_;
    float* xr = x + (size_t)r * C_;
    for (int c = threadIdx.x; c < C_; c += 256) xr[c] = te[c] + pe[c];
}

// ---------------------------------------------------------------------------
// Launch
// ---------------------------------------------------------------------------
extern "C" void kernel_launch(void* const* d_in, const int* in_sizes, int n_in,
                              void* d_out, int out_size)
{
    (void)in_sizes; (void)n_in; (void)out_size;
    const int*   idx = (const int*)d_in[0];
    const float* tok = (const float*)d_in[1];
    const float* pos = (const float*)d_in[2];
    const float* Wq  = (const float*)d_in[3];
    const float* Wk  = (const float*)d_in[4];
    const float* Wv  = (const float*)d_in[5];
    const float* Wp  = (const float*)d_in[6];
    const float* bp  = (const float*)d_in[7];
    const float* g1  = (const float*)d_in[8];
    const float* be1 = (const float*)d_in[9];
    const float* g2  = (const float*)d_in[10];
    const float* be2 = (const float*)d_in[11];
    const float* W1  = (const float*)d_in[12];
    const float* bb1 = (const float*)d_in[13];
    const float* W2  = (const float*)d_in[14];
    const float* bb2 = (const float*)d_in[15];
    const float* gf  = (const float*)d_in[16];
    const float* bf  = (const float*)d_in[17];
    const float* Wh  = (const float*)d_in[18];
    const float* bhd = (const float*)d_in[19];
    float* out = (float*)d_out;

    float  *x, *att;
    float2 *h2, *qkv2, *o2, *a12, *wcat2, *wp2, *w12, *w22, *wh2;
    cudaGetSymbolAddress((void**)&x,     g_x);
    cudaGetSymbolAddress((void**)&h2,    g_h2);
    cudaGetSymbolAddress((void**)&qkv2,  g_qkv2);
    cudaGetSymbolAddress((void**)&o2,    g_o2);
    cudaGetSymbolAddress((void**)&a12,   g_a12);
    cudaGetSymbolAddress((void**)&att,   g_att);
    cudaGetSymbolAddress((void**)&wcat2, g_wcat2);
    cudaGetSymbolAddress((void**)&wp2,   g_wp2);
    cudaGetSymbolAddress((void**)&w12,   g_w12);
    cudaGetSymbolAddress((void**)&w22,   g_w22);
    cudaGetSymbolAddress((void**)&wh2,   g_wh2);

    cudaFuncSetAttribute((const void*)gemm512,
                         cudaFuncAttributeMaxDynamicSharedMemorySize, (int)SMEM_BYTES);
    cudaFuncSetAttribute((const void*)gemm_av,
                         cudaFuncAttributeMaxDynamicSharedMemorySize, (int)SMEM_BYTES);

    const float att_scale = 0.03608439182435161f;  // 768^-0.5 (reference uses full C)
    const float* NOF = (const float*)0;

    embed_k<<<BT_, 256>>>(idx, tok, pos, x);

    // --- pre-split all weights (batched over layers) ---
    pack_qkv_split<<<(L_ * C_ * C_ + 255) / 256, 256>>>(Wq, Wk, Wv, wcat2);
    split_k<<<(L_ * C_ * C_  / 4 + 255) / 256, 256>>>(Wp, wp2, L_ * C_ * C_  / 4);
    split_k<<<(L_ * C_ * C4_ / 4 + 255) / 256, 256>>>(W1, w12, L_ * C_ * C4_ / 4);
    split_k<<<(L_ * C4_ * C_ / 4 + 255) / 256, 256>>>(W2, w22, L_ * C4_ * C_ / 4);
    split_k<<<(C_ * V_ / 4 + 255) / 256, 256>>>(Wh, wh2, C_ * V_ / 4);

    dim3 gqkv(C3_ / 128, BT_ / 128, 1);
    dim3 gcc (C_  / 128, BT_ / 128, 1);
    dim3 gsc (T_  / 128, T_  / 128, B_ * H_);
    dim3 gav (1,         T_  / 128, B_ * H_);
    dim3 gf1 (C4_ / 128, BT_ / 128, 1);

    for (int l = 0; l < L_; l++) {
        layernorm_split<<<BT_, 256>>>(x, g1 + l * C_, be1 + l * C_, h2);

        // qkv = h @ Wcat -> split [BT, 3C]
        gemm512<<<gqkv, 512, SMEM_BYTES>>>(h2, wcat2 + (size_t)l * C_ * C3_, (float*)qkv2,
                BT_, C3_, C_, C_, C3_, C3_,
                0, 0, 0, 0, 0, 0, 1, NOF, NOF, 1.f, 0, 0, 1, 0);

        // scores: Q @ K^T per (b,h) -> plain att, upper blocks skipped
        gemm512<<<gsc, 512, SMEM_BYTES>>>(qkv2, qkv2 + C_, att,
                T_, T_, HS_, C3_, C3_, T_,
                (long long)T_ * C3_, (long long)HS_,
                (long long)T_ * C3_, (long long)HS_,
                (long long)H_ * T_ * T_, (long long)T_ * T_, H_,
                NOF, NOF, att_scale, 0, 1, 0, 1);

        softmax_causal<<<B_ * H_ * T_, 256>>>(att);

        // AV: P @ V -> split o (causally clamped K)
        gemm_av<<<gav, 256, SMEM_BYTES>>>(att, qkv2 + 2 * C_, o2,
                T_, T_, C3_, C_,
                (long long)H_ * T_ * T_, (long long)T_ * T_,
                (long long)T_ * C3_, (long long)HS_,
                (long long)T_ * C_, (long long)HS_, H_);

        // x = x + o @ Wproj + bproj (plain out)
        gemm512<<<gcc, 512, SMEM_BYTES>>>(o2, wp2 + (size_t)l * C_ * C_, x,
                BT_, C_, C_, C_, C_, C_,
                0, 0, 0, 0, 0, 0, 1, bp + l * C_, x, 1.f, 0, 0, 0, 0);

        layernorm_split<<<BT_, 256>>>(x, g2 + l * C_, be2 + l * C_, h2);

        // a1 = gelu(h @ W1 + b1) -> split
        gemm512<<<gf1, 512, SMEM_BYTES>>>(h2, w12 + (size_t)l * C_ * C4_, (float*)a12,
                BT_, C4_, C_, C_, C4_, C4_,
                0, 0, 0, 0, 0, 0, 1, bb1 + l * C4_, NOF, 1.f, 1, 0, 1, 0);

        // x = x + a1 @ W2 + b2 (plain out)
        gemm512<<<gcc, 512, SMEM_BYTES>>>(a12, w22 + (size_t)l * C4_ * C_, x,
                BT_, C_, C4_, C4_, C_, C_,
                0, 0, 0, 0, 0, 0, 1, bb2 + l * C_, x, 1.f, 0, 0, 0, 0);
    }

    layernorm_split<<<BT_, 256>>>(x, gf, bf, h2);

    dim3 ghd(V_ / 128, BT_ / 128, 1);
    gemm512<<<ghd, 512, SMEM_BYTES>>>(h2, wh2, out,
            BT_, V_, C_, C_, V_, V_,
            0, 0, 0, 0, 0, 0, 1, bhd, NOF, 1.f, 0, 0, 0, 0);
}